// round 17
// baseline (speedup 1.0000x reference)
#include <cuda_runtime.h>
#include <cuda_bf16.h>

#define GG   256      // graphs
#define DD   128      // feature dim
#define ROWS_PER_WARP 128
#define ACC_THREADS   256   // 8 warps per CTA
#define FIN_CTAS 128        // single wave; 2 graphs per CTA

// Zero-initialized at module load; finalize_kernel re-zeros after consuming,
// so the invariant "scratch is zero at accum launch" holds on every replay.
__device__ float g_sums[GG * DD];
__device__ float g_counts[GG];

__device__ __forceinline__ int load_g(const void* batch, long long i, int is64) {
    if (is64) return (int)((const long long*)batch)[i];
    return ((const int*)batch)[i];
}

__device__ __forceinline__ void flush_seg(int g, float4 acc, int cnt, int lane) {
    if (cnt == 0) return;
    float* s = g_sums + (long long)g * DD + lane * 4;
    atomicAdd(s + 0, acc.x);
    atomicAdd(s + 1, acc.y);
    atomicAdd(s + 2, acc.z);
    atomicAdd(s + 3, acc.w);
    if (lane == 0) atomicAdd(&g_counts[g], (float)cnt);
}

// Streaming segment-sum — proven R9/R16 version (MLP=8 fast path, no launch
// bounds). Adds an early cudaTriggerProgrammaticLaunchCompletion() so the
// PDL-dependent finalize kernel can launch into freed SM slots during this
// kernel's drain tail (trigger fires once ALL accum CTAs have launched, so
// it never competes with pending accum CTAs).
__global__ void accum_kernel(const float4* __restrict__ x4,
                             const void* __restrict__ batch, int N) {
    cudaTriggerProgrammaticLaunchCompletion();

    // dtype probe: int32 word N-1 is the high half of int64 element 999,999 (=0)
    // if batch is int64, but the sorted max (>0) if int32.
    const int is64 = (((const int*)batch)[N - 1] == 0);
    const int lane = threadIdx.x & 31;
    const long long warp = (long long)(blockIdx.x * (ACC_THREADS / 32)) + (threadIdx.x >> 5);
    long long r0 = warp * ROWS_PER_WARP;
    if (r0 >= N) return;
    long long r1 = r0 + ROWS_PER_WARP;
    if (r1 > N) r1 = N;

    const int gfirst = load_g(batch, r0, is64);
    const int glast  = load_g(batch, r1 - 1, is64);

    if (gfirst == glast) {
        // ---- fast path: whole block in one segment, 8 LDG.128 in flight ----
        float4 acc = make_float4(0.f, 0.f, 0.f, 0.f);
        long long r = r0;
        for (; r + 8 <= r1; r += 8) {
            float4 v[8];
            #pragma unroll
            for (int k = 0; k < 8; k++)
                v[k] = __ldcs(&x4[(r + k) * 32 + lane]);   // evict-first stream
            #pragma unroll
            for (int k = 0; k < 8; k++) {
                acc.x += v[k].x; acc.y += v[k].y;
                acc.z += v[k].z; acc.w += v[k].w;
            }
        }
        for (; r < r1; r++) {
            float4 v = __ldcs(&x4[r * 32 + lane]);
            acc.x += v.x; acc.y += v.y; acc.z += v.z; acc.w += v.w;
        }
        flush_seg(gfirst, acc, (int)(r1 - r0), lane);
        return;
    }

    // ---- slow path: segment boundary inside this block (~2% of warps) ----
    float4 acc = make_float4(0.f, 0.f, 0.f, 0.f);
    int cnt = 0;
    int cur = gfirst;

    long long r = r0;
    for (; r + 4 <= r1; r += 4) {
        int ga = load_g(batch, r,     is64);
        int gd = load_g(batch, r + 3, is64);
        float4 v0 = __ldcs(&x4[(r    ) * 32 + lane]);
        float4 v1 = __ldcs(&x4[(r + 1) * 32 + lane]);
        float4 v2 = __ldcs(&x4[(r + 2) * 32 + lane]);
        float4 v3 = __ldcs(&x4[(r + 3) * 32 + lane]);
        if (ga == cur && gd == cur) {
            acc.x += (v0.x + v1.x) + (v2.x + v3.x);
            acc.y += (v0.y + v1.y) + (v2.y + v3.y);
            acc.z += (v0.z + v1.z) + (v2.z + v3.z);
            acc.w += (v0.w + v1.w) + (v2.w + v3.w);
            cnt += 4;
        } else {
            int gs[4];
            gs[0] = ga;
            gs[1] = load_g(batch, r + 1, is64);
            gs[2] = load_g(batch, r + 2, is64);
            gs[3] = gd;
            float4 vs[4] = {v0, v1, v2, v3};
            #pragma unroll
            for (int k = 0; k < 4; k++) {
                if (gs[k] != cur) {
                    flush_seg(cur, acc, cnt, lane);
                    acc = make_float4(0.f, 0.f, 0.f, 0.f);
                    cnt = 0;
                    cur = gs[k];
                }
                acc.x += vs[k].x; acc.y += vs[k].y;
                acc.z += vs[k].z; acc.w += vs[k].w;
                cnt++;
            }
        }
    }
    for (; r < r1; r++) {
        int g = load_g(batch, r, is64);
        float4 v = __ldcs(&x4[r * 32 + lane]);
        if (g != cur) {
            flush_seg(cur, acc, cnt, lane);
            acc = make_float4(0.f, 0.f, 0.f, 0.f);
            cnt = 0;
            cur = g;
        }
        acc.x += v.x; acc.y += v.y; acc.z += v.z; acc.w += v.w;
        cnt++;
    }
    flush_seg(cur, acc, cnt, lane);
}

// Mean + MLP head, PDL-overlapped. 128 CTAs x 256 threads, 2 graphs per CTA.
// PRELUDE (runs during accum's drain, before the dependency sync): stage all
// of W1 (32KB) into smem — this is the 5-6us cold-ramp cost that used to be
// serialized after accum. Then cudaGridDependencySynchronize() waits for
// accum completion (and makes its g_sums/g_counts writes visible), after
// which only ~1us of real work remains.
// Thread t: graph q = t>>7, half h = (t>>6)&1, unit j = t&63; 64-FMA LDS
// chain per thread, halves combined in smem; 1/count folded in post layer-1
// (linearity). Re-zeros its graphs' scratch for the next replay.
__global__ void finalize_kernel(const float* __restrict__ W1,
                                const float* __restrict__ b1,
                                const float* __restrict__ W2,
                                const float* __restrict__ b2,
                                float* __restrict__ out) {
    const int t = threadIdx.x;         // 0..255
    const int gbase = blockIdx.x * 2;  // graphs gbase, gbase+1
    __shared__ float w1s[DD * 64];     // 32 KB
    __shared__ float sum_s[2 * DD];
    __shared__ float hh[256];
    __shared__ float wpart[8];
    __shared__ float cnt_s[2];

    // ---- prelude: no dependence on accum output ----
    const float4* W14 = (const float4*)W1;     // 2048 float4
    float4 wv[8];
    #pragma unroll
    for (int i = 0; i < 8; i++) wv[i] = W14[t + i * 256];
    #pragma unroll
    for (int i = 0; i < 8; i++) ((float4*)w1s)[t + i * 256] = wv[i];

    // ---- wait for accum grid to complete (writes become visible) ----
    cudaGridDependencySynchronize();

    sum_s[t] = g_sums[gbase * DD + t];         // 256 floats = 2 graphs
    if (t < 2) cnt_s[t] = g_counts[gbase + t];
    __syncthreads();

    // restore zero-invariant for the next replay (all reads done above)
    g_sums[gbase * DD + t] = 0.0f;
    if (t < 2) g_counts[gbase + t] = 0.0f;

    // Layer 1, half-split: q = graph, h = d-half, j = hidden unit.
    const int j = t & 63;
    const int h = (t >> 6) & 1;
    const int q = t >> 7;
    const int dbase = h * 64;
    float acc = 0.0f;
    #pragma unroll
    for (int d0 = 0; d0 < 64; d0++) {
        int d = dbase + d0;
        acc = fmaf(sum_s[q * DD + d], w1s[d * 64 + j], acc);  // conflict-free LDS
    }
    hh[t] = acc;
    __syncthreads();

    // Combine halves + bias + relu + W2, then per-graph reduce (2 warps/graph).
    if (t < 128) {
        const int qq = t >> 6;
        const int jj = t & 63;
        float inv = 1.0f / cnt_s[qq];
        float hv = (hh[qq * 128 + jj] + hh[qq * 128 + 64 + jj]) * inv + b1[jj];
        hv = fmaxf(hv, 0.0f) * W2[jj];
        #pragma unroll
        for (int s = 16; s > 0; s >>= 1)
            hv += __shfl_down_sync(0xffffffffu, hv, s);
        if ((t & 31) == 0) wpart[t >> 5] = hv;
    }
    __syncthreads();
    if (t < 2) out[gbase + t] = wpart[2 * t] + wpart[2 * t + 1] + b2[0];
}

extern "C" void kernel_launch(void* const* d_in, const int* in_sizes, int n_in,
                              void* d_out, int out_size) {
    const float* x     = (const float*)d_in[0];
    const void*  batch = d_in[1];
    const float* W1    = (const float*)d_in[2];
    const float* b1    = (const float*)d_in[3];
    const float* W2    = (const float*)d_in[4];
    const float* b2    = (const float*)d_in[5];
    float* out = (float*)d_out;

    const int N = in_sizes[0] / DD;   // 2,000,000

    int warps = (N + ROWS_PER_WARP - 1) / ROWS_PER_WARP;
    int ctas  = (warps + (ACC_THREADS / 32) - 1) / (ACC_THREADS / 32);
    accum_kernel<<<ctas, ACC_THREADS>>>((const float4*)x, batch, N);

    // Launch finalize with programmatic dependent launch: it may begin
    // (and run its W1-staging prelude) while accum drains; the in-kernel
    // cudaGridDependencySynchronize() enforces the data dependency.
    cudaLaunchConfig_t cfg = {};
    cfg.gridDim  = dim3(FIN_CTAS);
    cfg.blockDim = dim3(256);
    cfg.dynamicSmemBytes = 0;
    cfg.stream = 0;   // legacy default stream — same one the harness captures
    cudaLaunchAttribute attr[1];
    attr[0].id = cudaLaunchAttributeProgrammaticStreamSerialization;
    attr[0].val.programmaticStreamSerializationAllowed = 1;
    cfg.attrs = attr;
    cfg.numAttrs = 1;
    cudaLaunchKernelEx(&cfg, finalize_kernel, W1, b1, W2, b2, out);
}